// round 17
// baseline (speedup 1.0000x reference)
#include <cuda_runtime.h>
#include <cuda_fp16.h>
#include <math.h>
#include <stdint.h>

#define NATOM 32768
#define MNBR 12
#define DIM 64
#define FNBR 41
#define ORIG 92
#define TWO_D 128
#define KTOT 169
#define NCRY 512
#define NA 64
#define CNT1F (393216.0f)
#define CNT2F (32768.0f)
#define EPSBN 1e-5f

#define K2N 88          // u32 (half2) count per B row: K=170 padded to 176 halves
#define AP 92           // A smem pitch in u32
#define BP 92           // B smem pitch in u32
#define NKS 11          // k-steps of 16
#define SPAD 32         // stat array stride (32 floats = 128B) to spread LTS slices
#define NTILE (NATOM * MNBR / 64)   // 6144 tiles
#define CZGRID 296                   // persistent CTAs (2/SM x 148)
#define ZBP 68          // z staging pitch in u32 (4q+r covers all banks)

// ---------------- scratch (device globals; no allocation) ----------------
__device__ float g_x[2][NATOM * DIM];
__device__ __align__(16) uint32_t g_xh[2][NATOM * 32];      // half2 mirror of x
__device__ __align__(16) uint32_t g_nfH[NATOM * MNBR * 24]; // [nbr_fea|1|pad] half2
__device__ uint32_t g_z[NATOM * MNBR * 64];          // z as half2, 100 MB
__device__ float g_summed[NATOM * DIM];
__device__ float g_G[NCRY * NA * 384];               // 50 MB
__device__ uint32_t g_WnH[3 * TWO_D * K2N];          // fused W half2 [l][n][k2]
__device__ float g_embT[ORIG * DIM];                 // [k][d]
__device__ float g_bilT[DIM * 6 * DIM];              // [d][o*64+k]
__device__ float g_fcaT[DIM * ORIG];                 // [k][c]
// padded stat arrays: one 128B line per channel -> many LTS slices
__device__ float g_s1[TWO_D * SPAD], g_ss1[TWO_D * SPAD];
__device__ float g_s2[DIM * SPAD], g_ss2[DIM * SPAD];

__device__ __forceinline__ float softplusf(float v) {
    return v > 20.0f ? v : log1pf(expf(v));
}
// fast softplus * sigmoid gate (approx intrinsics; err ~1e-6 rel, far below fp16 z noise)
__device__ __forceinline__ float gatef(float fv, float cv) {
    float sp = (cv > 15.0f) ? cv : __logf(1.0f + __expf(cv));
    return __fdividef(sp, 1.0f + __expf(-fv));
}
__device__ __forceinline__ void mma_f16(float* c, const uint32_t* a, const uint32_t* b) {
    asm volatile(
        "mma.sync.aligned.m16n8k16.row.col.f32.f16.f16.f32 "
        "{%0,%1,%2,%3}, {%4,%5,%6,%7}, {%8,%9}, {%0,%1,%2,%3};"
        : "+f"(c[0]), "+f"(c[1]), "+f"(c[2]), "+f"(c[3])
        : "r"(a[0]), "r"(a[1]), "r"(a[2]), "r"(a[3]), "r"(b[0]), "r"(b[1]));
}
__device__ __forceinline__ void ldsm4(uint32_t* r, uint32_t addr) {
    asm volatile("ldmatrix.sync.aligned.m8n8.x4.shared.b16 {%0,%1,%2,%3}, [%4];"
                 : "=r"(r[0]), "=r"(r[1]), "=r"(r[2]), "=r"(r[3]) : "r"(addr));
}
__device__ __forceinline__ void cpa16(uint32_t dst, const void* src) {
    asm volatile("cp.async.ca.shared.global [%0], [%1], 16;" :: "r"(dst), "l"(src));
}

// ---------------- prep: fused weight layout + half nbr_fea ----------------
__global__ void prep_kernel(const float* __restrict__ conv_W,
                            const float* __restrict__ conv_b,
                            const float* __restrict__ embed_W,
                            const float* __restrict__ bil_W,
                            const float* __restrict__ fca_W,
                            const float* __restrict__ nbr_fea) {
    int idx = blockIdx.x * blockDim.x + threadIdx.x;
    if (idx < 3 * TWO_D * K2N) {                      // g_WnH [l][n][j]
        int l = idx / (TWO_D * K2N), r = idx % (TWO_D * K2N);
        int n = r / K2N, j = r % K2N;
        int k0 = 2 * j, k1 = 2 * j + 1;
        const float* wr = conv_W + (l * TWO_D + n) * KTOT;
        float a = (k0 < KTOT) ? wr[k0] : (k0 == KTOT ? conv_b[l * TWO_D + n] : 0.f);
        float b = (k1 < KTOT) ? wr[k1] : (k1 == KTOT ? conv_b[l * TWO_D + n] : 0.f);
        __half2 h = __floats2half2_rn(a, b);
        g_WnH[idx] = *(uint32_t*)&h;
        return;
    }
    int i2 = idx - 3 * TWO_D * K2N;
    if (i2 < ORIG * DIM) {                            // g_embT [k][d]
        int k = i2 / DIM, d = i2 % DIM;
        g_embT[i2] = embed_W[d * ORIG + k];
        return;
    }
    int i3 = i2 - ORIG * DIM;
    if (i3 < DIM * 6 * DIM) {                         // g_bilT [d][o*64+k]
        int d = i3 / 384, ok = i3 % 384;
        int o = ok >> 6, k2 = ok & 63;
        g_bilT[i3] = bil_W[(o * DIM + d) * DIM + k2];
        return;
    }
    int i4 = i3 - DIM * 6 * DIM;
    if (i4 < DIM * ORIG) {
        int k = i4 / ORIG, c = i4 % ORIG;
        g_fcaT[i4] = fca_W[c * DIM + k];
        return;
    }
    int i5 = i4 - DIM * ORIG;
    if (i5 < NATOM * MNBR * 24) {                     // g_nfH [row][j]
        int row = i5 / 24, j = i5 % 24;
        int h0 = 2 * j, h1 = 2 * j + 1;
        const float* nf = nbr_fea + (long)row * FNBR;
        float a = (h0 < FNBR) ? nf[h0] : (h0 == FNBR ? 1.0f : 0.f);
        float b = (h1 < FNBR) ? nf[h1] : (h1 == FNBR ? 1.0f : 0.f);
        __half2 h = __floats2half2_rn(a, b);
        g_nfH[i5] = *(uint32_t*)&h;
    }
}

// ---------------- embedding: x = atom_fea @ embed_W^T  (K=92); also writes half mirror ----------------
__global__ __launch_bounds__(256) void embed_kernel(const float* __restrict__ atom_fea) {
    __shared__ float As[64 * ORIG];
    __shared__ float Ws[ORIG * DIM];
    int t = threadIdx.x;
    int rb = blockIdx.x * 64;
    for (int e = t; e < ORIG * DIM; e += 256) Ws[e] = g_embT[e];
    int warp = t >> 5, lane = t & 31;
    for (int m = warp; m < 64; m += 8) {
        const float* row = atom_fea + (rb + m) * ORIG;
        As[m * ORIG + lane] = row[lane];
        As[m * ORIG + 32 + lane] = row[32 + lane];
        if (lane < ORIG - 64) As[m * ORIG + 64 + lane] = row[64 + lane];
    }
    __syncthreads();
    int ty = t >> 5, tx = t & 31;
    float acc[8][2];
#pragma unroll
    for (int i = 0; i < 8; i++) { acc[i][0] = 0.f; acc[i][1] = 0.f; }
    for (int k = 0; k < ORIG; k++) {
        float2 b = *(const float2*)&Ws[k * DIM + tx * 2];
#pragma unroll
        for (int i = 0; i < 8; i++) {
            float a = As[(ty * 8 + i) * ORIG + k];
            acc[i][0] = fmaf(a, b.x, acc[i][0]);
            acc[i][1] = fmaf(a, b.y, acc[i][1]);
        }
    }
#pragma unroll
    for (int i = 0; i < 8; i++) {
        int row = rb + ty * 8 + i;
        *(float2*)&g_x[0][row * DIM + tx * 2] = make_float2(acc[i][0], acc[i][1]);
        __half2 h = __floats2half2_rn(acc[i][0], acc[i][1]);
        g_xh[0][row * 32 + tx] = *(uint32_t*)&h;
    }
}

// ---------------- stat zeroing (padded arrays; every layer) ----------------
__global__ void zero_stats() {
    int t = blockIdx.x * 256 + threadIdx.x;
    if (t < TWO_D * SPAD) { g_s1[t] = 0.f; g_ss1[t] = 0.f; }
    int u = t - TWO_D * SPAD;
    if (u >= 0 && u < DIM * SPAD) { g_s2[u] = 0.f; g_ss2[u] = 0.f; }
}

// ---------------- fused conv GEMM (persistent CTAs, 2-stage pipelined A-gather) ----------------
#define CZ_SMEM ((2 * 64 * AP + 128 * BP) * 4)

__global__ __launch_bounds__(256, 2) void convz_kernel(int l, int buf,
                                                       const int* __restrict__ nbr_idx) {
    extern __shared__ uint32_t smu[];
    // Abuf[2]: [64][AP] each; zbuf reuses current Abuf
    uint32_t* Bs2 = smu + 2 * 64 * AP;   // [128][BP]
    __shared__ float redS[128], redQ[128];
    int t = threadIdx.x, w = t >> 5, lane = t & 31;
    const uint32_t* xh = g_xh[buf];
    if (t < 128) { redS[t] = 0.f; redQ[t] = 0.f; }
    // B: load fused weights ONCE per persistent CTA
    {
        const uint32_t* src = g_WnH + l * TWO_D * K2N;
        for (int e = t; e < TWO_D * K2N; e += 256)
            Bs2[(e / K2N) * BP + (e % K2N)] = src[e];
    }

    int wm = w & 1, wn = w >> 1;             // wm 0..1 (32 rows), wn 0..3 (32 cols)
    int q = lane >> 2, r = lane & 3;
    uint32_t sAs = (uint32_t)__cvta_generic_to_shared(smu);
    uint32_t sBs = (uint32_t)__cvta_generic_to_shared(Bs2);
    uint32_t aOff = (((wm * 32) + (lane & 7) + ((lane >> 3) & 1) * 8) * AP +
                    ((lane >> 4) & 1) * 4) * 4;
    uint32_t bAddr0 = sBs + (((wn * 32) + (lane & 7) + ((lane >> 4) & 1) * 8) * BP +
                             ((lane >> 3) & 1) * 4) * 4;
    uint32_t bAddr1 = bAddr0 + 16 * BP * 4;

    // gather one tile's A into buffer bsel (cp.async; nbr via lane0 LDG+shfl)
    auto issue_tile = [&](int tile, int bsel) {
        int rb = tile * 64;
        uint32_t base = sAs + bsel * 64 * AP * 4;
        for (int m = w; m < 64; m += 8) {
            int row = rb + m;
            int nbr = 0;
            if (lane == 0) nbr = nbr_idx[row];
            nbr = __shfl_sync(0xffffffffu, nbr, 0);
            int nself = row / MNBR;
            uint32_t dstb = base + m * AP * 4;
            if (lane < 8) {
                cpa16(dstb + lane * 16, xh + nself * 32 + lane * 4);
            } else if (lane < 16) {
                cpa16(dstb + 128 + (lane - 8) * 16, xh + nbr * 32 + (lane - 8) * 4);
            } else if (lane < 22) {
                cpa16(dstb + 256 + (lane - 16) * 16, g_nfH + (long)row * 24 + (lane - 16) * 4);
            }
        }
    };

    int cur = 0;
    issue_tile(blockIdx.x, 0);
    asm volatile("cp.async.commit_group;" ::: "memory");

    for (int tile = blockIdx.x; tile < NTILE; tile += CZGRID) {
        int rb = tile * 64;
        int nxt = tile + CZGRID;
        if (nxt < NTILE) {
            issue_tile(nxt, cur ^ 1);
            asm volatile("cp.async.commit_group;" ::: "memory");
            asm volatile("cp.async.wait_group 1;" ::: "memory");
        } else {
            asm volatile("cp.async.wait_group 0;" ::: "memory");
        }
        __syncthreads();   // A(cur) visible to all warps

        uint32_t aAddr0 = sAs + cur * 64 * AP * 4 + aOff;
        uint32_t aAddr1 = aAddr0 + 16 * AP * 4;
        float c[2][4][4];
#pragma unroll
        for (int mt = 0; mt < 2; mt++)
#pragma unroll
            for (int nf = 0; nf < 4; nf++)
#pragma unroll
                for (int e = 0; e < 4; e++) c[mt][nf][e] = 0.f;

#pragma unroll
        for (int ks = 0; ks < NKS; ks++) {
            uint32_t ko = ks * 32;               // 8 u32 per step
            uint32_t a[2][4], b01[4], b23[4];
            ldsm4(a[0], aAddr0 + ko);
            ldsm4(a[1], aAddr1 + ko);
            ldsm4(b01, bAddr0 + ko);
            ldsm4(b23, bAddr1 + ko);
            uint32_t bf[4][2] = {{b01[0], b01[1]}, {b01[2], b01[3]},
                                 {b23[0], b23[1]}, {b23[2], b23[3]}};
#pragma unroll
            for (int mt = 0; mt < 2; mt++)
#pragma unroll
                for (int nf = 0; nf < 4; nf++)
                    mma_f16(c[mt][nf], a[mt], bf[nf]);
        }
        __syncthreads();   // all warps done reading A(cur) via ldmatrix

        // epilogue: half2 round-trip, stats in registers, stage z in A(cur) (bank-clean)
        uint32_t* zbuf = smu + cur * 64 * AP;   // [64][ZBP]
#pragma unroll
        for (int nf = 0; nf < 4; nf++) {
            int cc = wn * 32 + nf * 8 + r * 2;
            int cu = cc >> 1;
            float s0 = 0.f, s1 = 0.f, q0 = 0.f, q1 = 0.f;
#pragma unroll
            for (int mt = 0; mt < 2; mt++) {
                int m0 = wm * 32 + mt * 16 + q;
                __half2 h0 = __floats2half2_rn(c[mt][nf][0], c[mt][nf][1]);
                __half2 h1 = __floats2half2_rn(c[mt][nf][2], c[mt][nf][3]);
                zbuf[m0 * ZBP + cu] = *(uint32_t*)&h0;
                zbuf[(m0 + 8) * ZBP + cu] = *(uint32_t*)&h1;
                float2 v0 = __half22float2(h0);
                float2 v1 = __half22float2(h1);
                s0 += v0.x + v1.x; q0 += v0.x * v0.x + v1.x * v1.x;
                s1 += v0.y + v1.y; q1 += v0.y * v0.y + v1.y * v1.y;
            }
#pragma unroll
            for (int off = 4; off < 32; off <<= 1) {
                s0 += __shfl_xor_sync(0xffffffffu, s0, off);
                s1 += __shfl_xor_sync(0xffffffffu, s1, off);
                q0 += __shfl_xor_sync(0xffffffffu, q0, off);
                q1 += __shfl_xor_sync(0xffffffffu, q1, off);
            }
            if (lane < 4) {
                atomicAdd(&redS[cc], s0);
                atomicAdd(&redS[cc + 1], s1);
                atomicAdd(&redQ[cc], q0);
                atomicAdd(&redQ[cc + 1], q1);
            }
        }
        __syncthreads();   // zbuf complete
        // coalesced z store: 4 x uint4 per thread (128B sectors)
#pragma unroll
        for (int e = 0; e < 4; e++) {
            int idx = e * 256 + t;          // 0..1023 uint4 slots
            int row = idx >> 4;             // 64 rows
            int c4 = (idx & 15) * 4;        // 16 uint4 per row
            uint4 v = *(uint4*)&zbuf[row * ZBP + c4];
            *(uint4*)&g_z[((long)(rb + row)) * 64 + c4] = v;
        }
        __syncthreads();   // zbuf reads done before next iter's issue reuses it
        cur ^= 1;
    }
    // one global-atomic flush per persistent CTA
    if (t < 128) {
        atomicAdd(&g_s1[t * SPAD], redS[t]);
        atomicAdd(&g_ss1[t * SPAD], redQ[t]);
    }
}

// ---------------- BN1 + gate + sum over neighbors (half2 z), BN2 stats ----------------
__global__ __launch_bounds__(256) void reduce_kernel(int l,
                                                     const float* __restrict__ bn1_g,
                                                     const float* __restrict__ bn1_b) {
    __shared__ float r2S[64], r2Q[64];
    int c = threadIdx.x & 31, grp = threadIdx.x >> 5;
    int d0 = 2 * c;
    if (threadIdx.x < 64) { r2S[threadIdx.x] = 0.f; r2Q[threadIdx.x] = 0.f; }
    __syncthreads();
    float inv = 1.0f / CNT1F;
    float mf0 = g_s1[d0 * SPAD] * inv, mf1 = g_s1[(d0 + 1) * SPAD] * inv;
    float vf0 = g_ss1[d0 * SPAD] * inv - mf0 * mf0;
    float vf1 = g_ss1[(d0 + 1) * SPAD] * inv - mf1 * mf1;
    float scf0 = rsqrtf(vf0 + EPSBN) * bn1_g[l * TWO_D + d0];
    float scf1 = rsqrtf(vf1 + EPSBN) * bn1_g[l * TWO_D + d0 + 1];
    float shf0 = bn1_b[l * TWO_D + d0] - mf0 * scf0;
    float shf1 = bn1_b[l * TWO_D + d0 + 1] - mf1 * scf1;
    float mc0 = g_s1[(64 + d0) * SPAD] * inv, mc1 = g_s1[(64 + d0 + 1) * SPAD] * inv;
    float vc0 = g_ss1[(64 + d0) * SPAD] * inv - mc0 * mc0;
    float vc1 = g_ss1[(64 + d0 + 1) * SPAD] * inv - mc1 * mc1;
    float scc0 = rsqrtf(vc0 + EPSBN) * bn1_g[l * TWO_D + 64 + d0];
    float scc1 = rsqrtf(vc1 + EPSBN) * bn1_g[l * TWO_D + 64 + d0 + 1];
    float shc0 = bn1_b[l * TWO_D + 64 + d0] - mc0 * scc0;
    float shc1 = bn1_b[l * TWO_D + 64 + d0 + 1] - mc1 * scc1;

    float ls0 = 0.f, ls1 = 0.f, lq0 = 0.f, lq1 = 0.f;
    int n0 = blockIdx.x * 16 + grp * 2;
#pragma unroll
    for (int a = 0; a < 2; a++) {
        int n = n0 + a;
        const uint32_t* zr = g_z + (long)n * MNBR * 64;
        uint32_t zfp[MNBR], zcp[MNBR];
#pragma unroll
        for (int m = 0; m < MNBR; m++) zfp[m] = __ldg(&zr[m * 64 + c]);
#pragma unroll
        for (int m = 0; m < MNBR; m++) zcp[m] = __ldg(&zr[m * 64 + 32 + c]);
        float a0 = 0.f, a1 = 0.f;
#pragma unroll
        for (int m = 0; m < MNBR; m++) {
            float2 zf = __half22float2(*(__half2*)&zfp[m]);
            float2 zc = __half22float2(*(__half2*)&zcp[m]);
            a0 += gatef(zf.x * scf0 + shf0, zc.x * scc0 + shc0);
            a1 += gatef(zf.y * scf1 + shf1, zc.y * scc1 + shc1);
        }
        *(float2*)&g_summed[n * DIM + d0] = make_float2(a0, a1);
        ls0 += a0; lq0 += a0 * a0;
        ls1 += a1; lq1 += a1 * a1;
    }
    // stage BN2 stats in smem (8 warps share channels), then 1 global atomic/ch/block
    atomicAdd(&r2S[d0], ls0);
    atomicAdd(&r2S[d0 + 1], ls1);
    atomicAdd(&r2Q[d0], lq0);
    atomicAdd(&r2Q[d0 + 1], lq1);
    __syncthreads();
    if (threadIdx.x < 64) {
        atomicAdd(&g_s2[threadIdx.x * SPAD], r2S[threadIdx.x]);
        atomicAdd(&g_ss2[threadIdx.x * SPAD], r2Q[threadIdx.x]);
    }
}

// ---------------- BN2 + residual softplus -> x_out (fp32 + half mirror) ----------------
__global__ __launch_bounds__(256) void bnres_kernel(int l, int buf,
                                                    const float* __restrict__ bn2_g,
                                                    const float* __restrict__ bn2_b) {
    int gid2 = blockIdx.x * 256 + threadIdx.x;       // one per 2 elements
    int n = gid2 >> 5;
    int d0 = (gid2 & 31) * 2;
    float inv = 1.0f / CNT2F;
    float m0 = g_s2[d0 * SPAD] * inv, m1 = g_s2[(d0 + 1) * SPAD] * inv;
    float v0 = g_ss2[d0 * SPAD] * inv - m0 * m0;
    float v1 = g_ss2[(d0 + 1) * SPAD] * inv - m1 * m1;
    float sc0 = rsqrtf(v0 + EPSBN) * bn2_g[l * DIM + d0];
    float sc1 = rsqrtf(v1 + EPSBN) * bn2_g[l * DIM + d0 + 1];
    float sh0 = bn2_b[l * DIM + d0] - m0 * sc0;
    float sh1 = bn2_b[l * DIM + d0 + 1] - m1 * sc1;
    float2 xo = *(const float2*)&g_x[buf][n * DIM + d0];
    float2 sm = *(const float2*)&g_summed[n * DIM + d0];
    float a = xo.x + sm.x * sc0 + sh0;
    float b = xo.y + sm.y * sc1 + sh1;
    a = (a > 15.0f) ? a : __logf(1.0f + __expf(a));
    b = (b > 15.0f) ? b : __logf(1.0f + __expf(b));
    *(float2*)&g_x[1 - buf][n * DIM + d0] = make_float2(a, b);
    __half2 h = __floats2half2_rn(a, b);
    g_xh[1 - buf][n * 32 + (d0 >> 1)] = *(uint32_t*)&h;
}

// ---------------- G[bi, o*64+k] = f[bi,:] @ bilT  (K=64, scalar) ----------------
__global__ __launch_bounds__(256) void gmat_kernel(int buf, const int* __restrict__ cidx) {
    extern __shared__ float sm[];
    float* Ws = sm;                // [64][128]
    float* As = sm + 64 * TWO_D;   // [64][64]
    __shared__ int cid_s[64];
    int t = threadIdx.x;
    int rb = blockIdx.x * 64;
    int co = blockIdx.y * 128;
    const float* x = g_x[buf];
    if (t < 64) cid_s[t] = cidx[rb + t];
    for (int e = t; e < 64 * TWO_D; e += 256) {
        int k = e >> 7, oc = e & 127;
        Ws[e] = g_bilT[k * 384 + co + oc];
    }
    __syncthreads();
    int warp = t >> 5, lane = t & 31;
    for (int m = warp; m < 64; m += 8) {
        int a = cid_s[m];
        As[m * 64 + lane]      = x[a * DIM + lane];
        As[m * 64 + 32 + lane] = x[a * DIM + 32 + lane];
    }
    __syncthreads();
    int ty = t >> 5, tx = t & 31;
    float acc[8][4];
#pragma unroll
    for (int i = 0; i < 8; i++)
#pragma unroll
        for (int c = 0; c < 4; c++) acc[i][c] = 0.f;
    for (int k = 0; k < 64; k++) {
        float4 b = *(const float4*)&Ws[k * TWO_D + tx * 4];
#pragma unroll
        for (int i = 0; i < 8; i++) {
            float a = As[(ty * 8 + i) * 64 + k];
            acc[i][0] = fmaf(a, b.x, acc[i][0]);
            acc[i][1] = fmaf(a, b.y, acc[i][1]);
            acc[i][2] = fmaf(a, b.z, acc[i][2]);
            acc[i][3] = fmaf(a, b.w, acc[i][3]);
        }
    }
#pragma unroll
    for (int i = 0; i < 8; i++)
        *(float4*)&g_G[(long)(rb + ty * 8 + i) * 384 + co + tx * 4] =
            make_float4(acc[i][0], acc[i][1], acc[i][2], acc[i][3]);
}

// ---------------- edge: per-pair bilinear dot + fc1 + log_softmax ----------------
__global__ __launch_bounds__(256) void edge_kernel(int buf, const int* __restrict__ cidx,
                                                   const float* __restrict__ bil_b,
                                                   const float* __restrict__ fc1_W,
                                                   const float* __restrict__ fc1_b,
                                                   float* __restrict__ out) {
    __shared__ float f_s[64][65];
    __shared__ float Gi[4][384];
    __shared__ int cid_s[64];
    __shared__ float s_fc1W[36], s_fc1b[6], s_bilb[6];
    int b = blockIdx.x, it = blockIdx.y, t = threadIdx.x;
    const float* x = g_x[buf];
    if (t < 64) cid_s[t] = cidx[b * 64 + t];
    if (t < 36) s_fc1W[t] = fc1_W[t];
    if (t >= 64 && t < 70) s_fc1b[t - 64] = fc1_b[t - 64];
    if (t >= 96 && t < 102) s_bilb[t - 96] = bil_b[t - 96];
    __syncthreads();
    for (int e = t; e < 4096; e += 256) {
        int m = e >> 6, k = e & 63;
        f_s[m][k] = x[cid_s[m] * DIM + k];
    }
    for (int e = t; e < 1536; e += 256) {
        int i4 = e / 384, ok = e % 384;
        Gi[i4][ok] = g_G[(long)(b * 64 + it * 4 + i4) * 384 + ok];
    }
    __syncthreads();
    int i4 = t >> 6, j = t & 63;
    float ev[6];
#pragma unroll
    for (int o = 0; o < 6; o++) {
        float a = s_bilb[o];
#pragma unroll 16
        for (int k = 0; k < 64; k++) a = fmaf(Gi[i4][o * 64 + k], f_s[j][k], a);
        ev[o] = a;
    }
    float tr[6];
#pragma unroll
    for (int r = 0; r < 6; r++) {
        float a = s_fc1b[r];
#pragma unroll
        for (int o = 0; o < 6; o++) a = fmaf(s_fc1W[r * 6 + o], ev[o], a);
        tr[r] = a;
    }
    float mx = tr[0];
#pragma unroll
    for (int r = 1; r < 6; r++) mx = fmaxf(mx, tr[r]);
    float se = 0.f;
#pragma unroll
    for (int r = 0; r < 6; r++) se += expf(tr[r] - mx);
    float lse = mx + logf(se);
    int pair = (it * 4 + i4) * 64 + j;
    float* op = out + ((long)b * 4096 + pair) * 6;
#pragma unroll
    for (int r = 0; r < 6; r++) op[r] = tr[r] - lse;
}

// ---------------- atom_out = f @ fca_W^T + fca_b ----------------
__global__ __launch_bounds__(96) void atomout_kernel(int buf, const int* __restrict__ cidx,
                                                     const float* __restrict__ fca_b,
                                                     float* __restrict__ out2) {
    __shared__ float xr[64];
    int t = threadIdx.x;
    int r = blockIdx.x;
    int atom = cidx[r];
    if (t < 64) xr[t] = g_x[buf][atom * DIM + t];
    __syncthreads();
    if (t < ORIG) {
        float a = fca_b[t];
#pragma unroll 16
        for (int k = 0; k < 64; k++) a = fmaf(xr[k], g_fcaT[k * ORIG + t], a);
        out2[(long)r * ORIG + t] = a;
    }
}

// ---------------- launch ----------------
#define ZS_SM ((64 * TWO_D + 64 * 64) * 4)

extern "C" void kernel_launch(void* const* d_in, const int* in_sizes, int n_in,
                              void* d_out, int out_size) {
    (void)in_sizes; (void)n_in; (void)out_size;
    const float* atom_fea = (const float*)d_in[0];
    const float* nbr_fea  = (const float*)d_in[1];
    const int*   nbr_idx  = (const int*)d_in[2];
    const int*   cidx     = (const int*)d_in[3];
    const float* embed_W  = (const float*)d_in[4];
    const float* conv_W   = (const float*)d_in[5];
    const float* conv_b   = (const float*)d_in[6];
    const float* bn1_g    = (const float*)d_in[7];
    const float* bn1_b    = (const float*)d_in[8];
    const float* bn2_g    = (const float*)d_in[9];
    const float* bn2_b    = (const float*)d_in[10];
    const float* bil_W    = (const float*)d_in[11];
    const float* bil_b    = (const float*)d_in[12];
    const float* fc1_W    = (const float*)d_in[13];
    const float* fc1_b    = (const float*)d_in[14];
    const float* fca_W    = (const float*)d_in[15];
    const float* fca_b    = (const float*)d_in[16];
    float* out = (float*)d_out;

    cudaFuncSetAttribute(convz_kernel, cudaFuncAttributeMaxDynamicSharedMemorySize, CZ_SMEM);
    cudaFuncSetAttribute(gmat_kernel,  cudaFuncAttributeMaxDynamicSharedMemorySize, ZS_SM);

    long prep_elems = (long)3 * TWO_D * K2N + ORIG * DIM + DIM * 384 + DIM * ORIG +
                      (long)NATOM * MNBR * 24;
    prep_kernel<<<(int)((prep_elems + 255) / 256), 256>>>(conv_W, conv_b, embed_W, bil_W,
                                                          fca_W, nbr_fea);
    embed_kernel<<<NATOM / 64, 256>>>(atom_fea);

    int zs_blocks = (TWO_D * SPAD + DIM * SPAD + 255) / 256;
    int buf = 0;
    for (int l = 0; l < 3; l++) {
        zero_stats<<<zs_blocks, 256>>>();
        convz_kernel<<<CZGRID, 256, CZ_SMEM>>>(l, buf, nbr_idx);
        reduce_kernel<<<NATOM / 16, 256>>>(l, bn1_g, bn1_b);
        bnres_kernel<<<(NATOM * DIM / 2) / 256, 256>>>(l, buf, bn2_g, bn2_b);
        buf = 1 - buf;
    }

    gmat_kernel<<<dim3(NCRY * NA / 64, 3), 256, ZS_SM>>>(buf, cidx);
    edge_kernel<<<dim3(NCRY, 16), 256>>>(buf, cidx, bil_b, fc1_W, fc1_b, out);
    atomout_kernel<<<NCRY * NA, 96>>>(buf, cidx, fca_b, out + (long)NCRY * NA * NA * 6);
}